// round 11
// baseline (speedup 1.0000x reference)
#include <cuda_runtime.h>
#include <cuda_bf16.h>
#include <cstdint>

#define HWsz 16384
#define NPIX (8 * HWsz)   // 131072 pixels

// -------- scratch --------
__device__ float            g_xt[(size_t)NPIX * 64];    // NHWC x (f32, for deform bilinear blend)
__device__ __nv_bfloat16    g_xh[(size_t)NPIX * 64];    // NHWC x bf16 hi
__device__ __nv_bfloat16    g_xl[(size_t)NPIX * 64];    // NHWC x bf16 lo
__device__ __align__(16) uint32_t g_wqs[9 * 4096];      // deform W: per tap 16KB (hi 8KB + lo 8KB), 64x64 bf16 SW128
__device__ __align__(16) uint32_t g_wom[9 * 2048];      // conv W: per tap 8KB (hi 4KB + lo 4KB), 32x64 bf16 SW128
__device__ int4   g_ci2[(size_t)9 * NPIX];              // corner indices, [tap][pixel]
__device__ float4 g_cw2[(size_t)9 * NPIX];              // corner weights, [tap][pixel]

// -------- helpers --------
__device__ __forceinline__ uint32_t smem_u32(const void* p) {
    return (uint32_t)__cvta_generic_to_shared(p);
}
__device__ __forceinline__ void sts64(uint32_t addr, uint32_t a, uint32_t b) {
    asm volatile("st.shared.v2.b32 [%0], {%1, %2};" :: "r"(addr), "r"(a), "r"(b) : "memory");
}
__device__ __forceinline__ uint32_t bf16x2_of(float hi, float lo) {
    uint32_t r; asm("cvt.rn.bf16x2.f32 %0, %1, %2;" : "=r"(r) : "f"(hi), "f"(lo)); return r;
}
__device__ __forceinline__ uint32_t sw128(uint32_t off) { return off ^ ((off >> 3) & 0x70); }

__device__ __forceinline__ void ldsm4(uint32_t addr, uint32_t& r0, uint32_t& r1, uint32_t& r2, uint32_t& r3) {
    asm volatile("ldmatrix.sync.aligned.m8n8.x4.shared.b16 {%0,%1,%2,%3}, [%4];"
                 : "=r"(r0), "=r"(r1), "=r"(r2), "=r"(r3) : "r"(addr));
}
__device__ __forceinline__ void mma16816(float* d, uint32_t a0, uint32_t a1, uint32_t a2, uint32_t a3,
                                         uint32_t b0, uint32_t b1) {
    asm volatile("mma.sync.aligned.m16n8k16.row.col.f32.bf16.bf16.f32 "
                 "{%0,%1,%2,%3}, {%4,%5,%6,%7}, {%8,%9}, {%0,%1,%2,%3};"
                 : "+f"(d[0]), "+f"(d[1]), "+f"(d[2]), "+f"(d[3])
                 : "r"(a0), "r"(a1), "r"(a2), "r"(a3), "r"(b0), "r"(b1));
}
__device__ __forceinline__ void hilo_pack(float r0, float r1, uint32_t& h, uint32_t& l) {
    h = bf16x2_of(r1, r0);
    float hi0 = __uint_as_float(h << 16);
    float hi1 = __uint_as_float(h & 0xFFFF0000u);
    l = bf16x2_of(r1 - hi1, r0 - hi0);
}
__device__ __forceinline__ void cpasync16(uint32_t dst, const void* src, int srcsize) {
    asm volatile("cp.async.ca.shared.global [%0], [%1], 16, %2;"
                 :: "r"(dst), "l"(src), "r"(srcsize) : "memory");
}
__device__ __forceinline__ void cpcommit() { asm volatile("cp.async.commit_group;" ::: "memory"); }
__device__ __forceinline__ void cpwait0()  { asm volatile("cp.async.wait_group 0;" ::: "memory"); }

// ---------------- kernel 1: NCHW -> NHWC (f32 + bf16 hi/lo) ----------------
__global__ void __launch_bounds__(256) k_transpose(const float* __restrict__ x) {
    __shared__ float sh[64][33];
    int blk = blockIdx.x;
    int b   = blk >> 9;
    int hw0 = (blk & 511) << 5;
    int t = threadIdx.x;
#pragma unroll
    for (int i = 0; i < 8; i++) {
        int e = t + i * 256;
        int c = e >> 5, wp = e & 31;
        sh[c][wp] = x[((size_t)(b * 64 + c) << 14) + hw0 + wp];
    }
    __syncthreads();
#pragma unroll
    for (int i = 0; i < 8; i++) {
        int e = t + i * 256;
        int wp = e >> 6, c = e & 63;
        float v = sh[c][wp];
        size_t idx = (((size_t)b << 14) + hw0 + wp) * 64 + c;
        g_xt[idx] = v;
        __nv_bfloat16 hb = __float2bfloat16(v);
        g_xh[idx] = hb;
        g_xl[idx] = __float2bfloat16(v - __bfloat162float(hb));
    }
}

// ---------------- kernel 2a: pack w_conv (deform B tiles, 64x64) ----------------
__global__ void k_wpack(const float* __restrict__ w_conv) {
    int t = blockIdx.x * 256 + threadIdx.x;
    if (t >= 9 * 4096) return;
    int tap = t >> 12;
    int r   = t & 4095;
    int o = r >> 6, c = r & 63;
    float w = w_conv[o * 576 + c * 9 + tap];
    __nv_bfloat16 hb = __float2bfloat16(w);
    __nv_bfloat16 lb = __float2bfloat16(w - __bfloat162float(hb));
    uint32_t swo = sw128(o * 128 + c * 2);
    char* base = (char*)g_wqs + tap * 16384;
    *(__nv_bfloat16*)(base + swo)        = hb;
    *(__nv_bfloat16*)(base + 8192 + swo) = lb;
}

// ---------------- kernel 2b: pack w_offset/w_mask (conv B tiles, 32x64) ----------------
__global__ void k_wpack2(const float* __restrict__ w_off, const float* __restrict__ w_msk) {
    int t = blockIdx.x * 256 + threadIdx.x;
    if (t >= 9 * 2048) return;
    int tap = t >> 11;
    int r   = t & 2047;
    int o = r >> 6, c = r & 63;
    float w = 0.f;
    if (o < 18)      w = w_off[o * 576 + c * 9 + tap];
    else if (o < 27) w = w_msk[(o - 18) * 576 + c * 9 + tap];
    __nv_bfloat16 hb = __float2bfloat16(w);
    __nv_bfloat16 lb = __float2bfloat16(w - __bfloat162float(hb));
    uint32_t swo = sw128(o * 128 + c * 2);
    char* base = (char*)g_wom + tap * 8192;
    *(__nv_bfloat16*)(base + swo)        = hb;
    *(__nv_bfloat16*)(base + 4096 + swo) = lb;
}

// ---------------- kernel 3: offset+mask conv via MMA, cp.async pipelined (unchanged R10) ----------------
#define C_A(s) ((s) * 32768)
#define C_B(s) (65536 + (s) * 8192)
#define CONV_SMEM 81920
__global__ void __launch_bounds__(256) k_conv() {
    extern __shared__ __align__(1024) char smem[];
    uint32_t sb = smem_u32(smem);

    int t = threadIdx.x, warp = t >> 5, lane = t & 31;
    int h = blockIdx.x & 127;
    int b = blockIdx.x >> 7;
    const __nv_bfloat16* xh = g_xh + ((size_t)b << 20);
    const __nv_bfloat16* xl = g_xl + ((size_t)b << 20);

    float d[4][4];
#pragma unroll
    for (int nb = 0; nb < 4; nb++)
#pragma unroll
        for (int i = 0; i < 4; i++) d[nb][i] = 0.f;

    int a_row = warp * 16 + (lane & 7) + ((lane >> 3) & 1) * 8;
    int a_kx  = ((lane >> 4) & 1) * 16;
    int b_row2 = ((lane >> 4) & 1) * 8 + (lane & 7);
    int b_kx2  = ((lane >> 3) & 1) * 16;

    auto copyA = [&](int tap, int s) {
        int dy = tap / 3 - 1, dx = tap % 3 - 1;
        int hh = h + dy;
        bool okh = (unsigned)hh < 128u;
        const __nv_bfloat16* rh = xh + ((size_t)(hh & 127) << 13);
        const __nv_bfloat16* rl = xl + ((size_t)(hh & 127) << 13);
        uint32_t dA = sb + C_A(s);
#pragma unroll
        for (int i = 0; i < 4; i++) {
            int u = i * 256 + t;
            int px = u >> 3, cg = u & 7;
            int sx = px + dx;
            int sz = (okh && (unsigned)sx < 128u) ? 16 : 0;
            int sxc = min(max(sx, 0), 127);
            uint32_t dsw = sw128((uint32_t)(px * 128 + cg * 16));
            cpasync16(dA + dsw,         (const char*)(rh + sxc * 64) + cg * 16, sz);
            cpasync16(dA + 16384 + dsw, (const char*)(rl + sxc * 64) + cg * 16, sz);
        }
    };
    auto copyB = [&](int tap, int s) {
        const char* src = (const char*)g_wom + tap * 8192;
        uint32_t dB = sb + C_B(s);
#pragma unroll
        for (int i = 0; i < 2; i++) {
            int u = i * 256 + t;
            cpasync16(dB + u * 16, src + u * 16, 16);
        }
    };

    copyA(0, 0); copyB(0, 0); cpcommit(); cpwait0();
    __syncthreads();

#pragma unroll 1
    for (int tap = 0; tap < 9; tap++) {
        int s = tap & 1;
        if (tap < 8) { copyA(tap + 1, s ^ 1); copyB(tap + 1, s ^ 1); cpcommit(); }
        uint32_t aB = sb + C_A(s), bB = sb + C_B(s);
#pragma unroll
        for (int kb = 0; kb < 4; kb++) {
            uint32_t aoff = sw128((uint32_t)(a_row * 128 + kb * 32 + a_kx));
            uint32_t ah0, ah1, ah2, ah3, al0, al1, al2, al3;
            ldsm4(aB + aoff, ah0, ah1, ah2, ah3);
            ldsm4(aB + 16384 + aoff, al0, al1, al2, al3);
#pragma unroll
            for (int nbp = 0; nbp < 2; nbp++) {
                uint32_t boff = sw128((uint32_t)((nbp * 16 + b_row2) * 128 + kb * 32 + b_kx2));
                uint32_t bh0, bh1, bh2, bh3, bl0, bl1, bl2, bl3;
                ldsm4(bB + boff, bh0, bh1, bh2, bh3);
                ldsm4(bB + 4096 + boff, bl0, bl1, bl2, bl3);
                mma16816(d[nbp * 2],     ah0, ah1, ah2, ah3, bh0, bh1);
                mma16816(d[nbp * 2],     ah0, ah1, ah2, ah3, bl0, bl1);
                mma16816(d[nbp * 2],     al0, al1, al2, al3, bh0, bh1);
                mma16816(d[nbp * 2 + 1], ah0, ah1, ah2, ah3, bh2, bh3);
                mma16816(d[nbp * 2 + 1], ah0, ah1, ah2, ah3, bl2, bl3);
                mma16816(d[nbp * 2 + 1], al0, al1, al2, al3, bh2, bh3);
            }
        }
        cpwait0();
        __syncthreads();
    }

    // transpose D through smem: sD[px][33]
    float* sD = (float*)smem;
    {
        int r0 = warp * 16 + (lane >> 2);
        int r1 = r0 + 8;
#pragma unroll
        for (int nb = 0; nb < 4; nb++) {
            int o0 = nb * 8 + (lane & 3) * 2;
            sD[r0 * 33 + o0]     = d[nb][0];
            sD[r0 * 33 + o0 + 1] = d[nb][1];
            sD[r1 * 33 + o0]     = d[nb][2];
            sD[r1 * 33 + o0 + 1] = d[nb][3];
        }
    }
    __syncthreads();

    if (t < 128) {
        int w = t;
        const float* rr = sD + t * 33;
        int p = b * 16384 + h * 128 + w;
#pragma unroll
        for (int k = 0; k < 9; k++) {
            float oy = rr[2 * k], ox = rr[2 * k + 1];
            float m  = 1.f / (1.f + __expf(-rr[18 + k]));
            float py = (float)(h + k / 3 - 1) + oy;
            float px = (float)(w + k % 3 - 1) + ox;
            float y0f = floorf(py), x0f = floorf(px);
            float wy1 = py - y0f, wy0 = 1.f - wy1;
            float wx1 = px - x0f, wx0 = 1.f - wx1;
            int y0 = (int)y0f, x0i = (int)x0f;
            int y1 = y0 + 1, x1i = x0i + 1;
            bool vy0 = (unsigned)y0  < 128u, vy1 = (unsigned)y1  < 128u;
            bool vx0 = (unsigned)x0i < 128u, vx1 = (unsigned)x1i < 128u;
            int cy0 = min(max(y0, 0), 127), cy1 = min(max(y1, 0), 127);
            int cx0 = min(max(x0i, 0), 127), cx1 = min(max(x1i, 0), 127);
            int4 ci; float4 cw;
            ci.x = cy0 * 128 + cx0; cw.x = (vy0 && vx0) ? m * wy0 * wx0 : 0.f;
            ci.y = cy0 * 128 + cx1; cw.y = (vy0 && vx1) ? m * wy0 * wx1 : 0.f;
            ci.z = cy1 * 128 + cx0; cw.z = (vy1 && vx0) ? m * wy1 * wx0 : 0.f;
            ci.w = cy1 * 128 + cx1; cw.w = (vy1 && vx1) ? m * wy1 * wx1 : 0.f;
            g_ci2[(size_t)k * NPIX + p] = ci;
            g_cw2[(size_t)k * NPIX + p] = cw;
        }
    }
}

// ---------------- kernel 4: deform, warp-specialized producer/consumer ----------------
// 384 threads: warps 0-7 = consumers (pure ldsm+mma on 128px x 64o), warps 8-11 =
// producers (gather tap+1 + B copy). smem: A 2x32KB + B 2x16KB = 96KB -> 2 CTA/SM.
#define D_A(s)  ((s) * 32768)
#define D_B(s)  (65536 + (s) * 16384)
#define DEF_SMEM 98304
__global__ void __launch_bounds__(384, 2) k_deform(float* __restrict__ out) {
    extern __shared__ __align__(1024) char smem[];
    uint32_t sb = smem_u32(smem);

    int t = threadIdx.x, warp = t >> 5, lane = t & 31;
    int P0 = blockIdx.x << 7;
    int b = P0 >> 14, hwbase = P0 & 16383;
    const float* xb = g_xt + ((size_t)b << 20);
    bool producer = (warp >= 8);

    // ---- producer gather: 128 producer threads, 16 slots each (slot = px*16+cg) ----
    auto gather_tap = [&](int tap, uint32_t dA) {
        int pt = t - 256;   // 0..127
        const int4*   ciP = g_ci2 + (size_t)tap * NPIX + P0;
        const float4* cwP = g_cw2 + (size_t)tap * NPIX + P0;
#pragma unroll 2
        for (int j = 0; j < 16; j += 2) {
            // two independent slots in flight
            int s0 = j * 128 + pt, s1 = (j + 1) * 128 + pt;
            int px0 = s0 >> 4, cg0 = s0 & 15;
            int px1 = s1 >> 4, cg1 = s1 & 15;
            int4   ci0 = ciP[px0], ci1 = ciP[px1];
            float4 cw0 = cwP[px0], cw1 = cwP[px1];
            float4 a0 = *((const float4*)(xb + ((size_t)ci0.x << 6)) + cg0);
            float4 a1 = *((const float4*)(xb + ((size_t)ci0.y << 6)) + cg0);
            float4 a2 = *((const float4*)(xb + ((size_t)ci0.z << 6)) + cg0);
            float4 a3 = *((const float4*)(xb + ((size_t)ci0.w << 6)) + cg0);
            float4 c0 = *((const float4*)(xb + ((size_t)ci1.x << 6)) + cg1);
            float4 c1 = *((const float4*)(xb + ((size_t)ci1.y << 6)) + cg1);
            float4 c2 = *((const float4*)(xb + ((size_t)ci1.z << 6)) + cg1);
            float4 c3 = *((const float4*)(xb + ((size_t)ci1.w << 6)) + cg1);
            {
                float r0 = cw0.x * a0.x + cw0.y * a1.x + cw0.z * a2.x + cw0.w * a3.x;
                float r1 = cw0.x * a0.y + cw0.y * a1.y + cw0.z * a2.y + cw0.w * a3.y;
                float r2 = cw0.x * a0.z + cw0.y * a1.z + cw0.z * a2.z + cw0.w * a3.z;
                float r3 = cw0.x * a0.w + cw0.y * a1.w + cw0.z * a2.w + cw0.w * a3.w;
                uint32_t h01, l01, h23, l23;
                hilo_pack(r0, r1, h01, l01);
                hilo_pack(r2, r3, h23, l23);
                uint32_t swo = sw128((uint32_t)(px0 * 128 + cg0 * 8));
                sts64(dA + swo, h01, h23);
                sts64(dA + 16384 + swo, l01, l23);
            }
            {
                float r0 = cw1.x * c0.x + cw1.y * c1.x + cw1.z * c2.x + cw1.w * c3.x;
                float r1 = cw1.x * c0.y + cw1.y * c1.y + cw1.z * c2.y + cw1.w * c3.y;
                float r2 = cw1.x * c0.z + cw1.y * c1.z + cw1.z * c2.z + cw1.w * c3.z;
                float r3 = cw1.x * c0.w + cw1.y * c1.w + cw1.z * c2.w + cw1.w * c3.w;
                uint32_t h01, l01, h23, l23;
                hilo_pack(r0, r1, h01, l01);
                hilo_pack(r2, r3, h23, l23);
                uint32_t swo = sw128((uint32_t)(px1 * 128 + cg1 * 8));
                sts64(dA + swo, h01, h23);
                sts64(dA + 16384 + swo, l01, l23);
            }
        }
    };
    auto copyB = [&](int tap, int s) {
        int pt = t - 256;   // 0..127 -> 1024 units over 8 iters
        const char* src = (const char*)g_wqs + tap * 16384;
        uint32_t dB = sb + D_B(s);
#pragma unroll
        for (int i = 0; i < 8; i++) {
            int u = i * 128 + pt;
            cpasync16(dB + u * 16, src + u * 16, 16);
        }
    };

    // consumer lane mapping
    int a_row = warp * 16 + (lane & 7) + ((lane >> 3) & 1) * 8;
    int a_kx  = ((lane >> 4) & 1) * 16;
    int b_row2 = ((lane >> 4) & 1) * 8 + (lane & 7);
    int b_kx2  = ((lane >> 3) & 1) * 16;

    float d[8][4];
#pragma unroll
    for (int nb = 0; nb < 8; nb++)
#pragma unroll
        for (int i = 0; i < 4; i++) d[nb][i] = 0.f;

    // ---- prologue: producers load B(0) + gather tap 0 into A(0) ----
    if (producer) {
        copyB(0, 0);
        cpcommit();
        gather_tap(0, sb + D_A(0));
        cpwait0();
    }
    __syncthreads();

    // ---- main loop ----
#pragma unroll 1
    for (int tap = 0; tap < 9; tap++) {
        int s = tap & 1;
        if (producer) {
            if (tap < 8) {
                copyB(tap + 1, s ^ 1);
                cpcommit();
                gather_tap(tap + 1, sb + D_A(s ^ 1));
                cpwait0();
            }
        } else {
            uint32_t aB = sb + D_A(s), bB = sb + D_B(s);
#pragma unroll
            for (int kb = 0; kb < 4; kb++) {
                uint32_t aoff = sw128((uint32_t)(a_row * 128 + kb * 32 + a_kx));
                uint32_t ah0, ah1, ah2, ah3, al0, al1, al2, al3;
                ldsm4(aB + aoff, ah0, ah1, ah2, ah3);
                ldsm4(aB + 16384 + aoff, al0, al1, al2, al3);
#pragma unroll
                for (int nbp = 0; nbp < 4; nbp++) {
                    uint32_t boff = sw128((uint32_t)((nbp * 16 + b_row2) * 128 + kb * 32 + b_kx2));
                    uint32_t bh0, bh1, bh2, bh3, bl0, bl1, bl2, bl3;
                    ldsm4(bB + boff, bh0, bh1, bh2, bh3);
                    ldsm4(bB + 8192 + boff, bl0, bl1, bl2, bl3);
                    mma16816(d[nbp * 2],     ah0, ah1, ah2, ah3, bh0, bh1);
                    mma16816(d[nbp * 2],     ah0, ah1, ah2, ah3, bl0, bl1);
                    mma16816(d[nbp * 2],     al0, al1, al2, al3, bh0, bh1);
                    mma16816(d[nbp * 2 + 1], ah0, ah1, ah2, ah3, bh2, bh3);
                    mma16816(d[nbp * 2 + 1], ah0, ah1, ah2, ah3, bl2, bl3);
                    mma16816(d[nbp * 2 + 1], al0, al1, al2, al3, bh2, bh3);
                }
            }
        }
        __syncthreads();
    }

    // ---- epilogue: consumers write D -> out (NCHW) ----
    if (!producer) {
        size_t bo = (size_t)b << 20;
        int r0 = hwbase + warp * 16 + (lane >> 2);
        int r1 = r0 + 8;
#pragma unroll
        for (int nb = 0; nb < 8; nb++) {
            int o0 = nb * 8 + (lane & 3) * 2;
            out[bo + (size_t)o0 * 16384 + r0]       = d[nb][0];
            out[bo + (size_t)(o0 + 1) * 16384 + r0] = d[nb][1];
            out[bo + (size_t)o0 * 16384 + r1]       = d[nb][2];
            out[bo + (size_t)(o0 + 1) * 16384 + r1] = d[nb][3];
        }
    }
}

// ---------------- launch ----------------
extern "C" void kernel_launch(void* const* d_in, const int* in_sizes, int n_in,
                              void* d_out, int out_size) {
    (void)in_sizes; (void)n_in; (void)out_size;
    const float* x      = (const float*)d_in[0];
    const float* w_conv = (const float*)d_in[1];
    const float* w_off  = (const float*)d_in[2];
    const float* w_msk  = (const float*)d_in[3];
    float* out = (float*)d_out;

    cudaFuncSetAttribute(k_conv,   cudaFuncAttributeMaxDynamicSharedMemorySize, CONV_SMEM);
    cudaFuncSetAttribute(k_deform, cudaFuncAttributeMaxDynamicSharedMemorySize, DEF_SMEM);

    k_transpose<<<4096, 256>>>(x);
    k_wpack<<<(9 * 4096 + 255) / 256, 256>>>(w_conv);
    k_wpack2<<<(9 * 2048 + 255) / 256, 256>>>(w_off, w_msk);
    k_conv<<<1024, 256, CONV_SMEM>>>();
    k_deform<<<1024, 384, DEF_SMEM>>>(out);
}

// round 12
// speedup vs baseline: 1.6682x; 1.6682x over previous
#include <cuda_runtime.h>
#include <cuda_bf16.h>
#include <cstdint>

#define HWsz 16384
#define NPIX (8 * HWsz)   // 131072 pixels

// -------- scratch --------
__device__ float            g_xt[(size_t)NPIX * 64];    // NHWC x (f32, for deform bilinear blend)
__device__ __nv_bfloat16    g_xh[(size_t)NPIX * 64];    // NHWC x bf16 hi
__device__ __nv_bfloat16    g_xl[(size_t)NPIX * 64];    // NHWC x bf16 lo
__device__ __align__(16) uint32_t g_wqs[9 * 4096];      // deform W: per tap 16KB (hi 8KB + lo 8KB), 64x64 bf16 SW128
__device__ __align__(16) uint32_t g_wom[9 * 2048];      // conv W: per tap 8KB (hi 4KB + lo 4KB), 32x64 bf16 SW128
__device__ int4   g_ci2[(size_t)9 * NPIX];              // corner indices, [tap][pixel]
__device__ float4 g_cw2[(size_t)9 * NPIX];              // corner weights, [tap][pixel]

// -------- helpers --------
__device__ __forceinline__ uint32_t smem_u32(const void* p) {
    return (uint32_t)__cvta_generic_to_shared(p);
}
__device__ __forceinline__ void sts64(uint32_t addr, uint32_t a, uint32_t b) {
    asm volatile("st.shared.v2.b32 [%0], {%1, %2};" :: "r"(addr), "r"(a), "r"(b) : "memory");
}
__device__ __forceinline__ uint32_t bf16x2_of(float hi, float lo) {
    uint32_t r; asm("cvt.rn.bf16x2.f32 %0, %1, %2;" : "=r"(r) : "f"(hi), "f"(lo)); return r;
}
__device__ __forceinline__ uint32_t sw128(uint32_t off) { return off ^ ((off >> 3) & 0x70); }

__device__ __forceinline__ void ldsm4(uint32_t addr, uint32_t& r0, uint32_t& r1, uint32_t& r2, uint32_t& r3) {
    asm volatile("ldmatrix.sync.aligned.m8n8.x4.shared.b16 {%0,%1,%2,%3}, [%4];"
                 : "=r"(r0), "=r"(r1), "=r"(r2), "=r"(r3) : "r"(addr));
}
__device__ __forceinline__ void mma16816(float* d, uint32_t a0, uint32_t a1, uint32_t a2, uint32_t a3,
                                         uint32_t b0, uint32_t b1) {
    asm volatile("mma.sync.aligned.m16n8k16.row.col.f32.bf16.bf16.f32 "
                 "{%0,%1,%2,%3}, {%4,%5,%6,%7}, {%8,%9}, {%0,%1,%2,%3};"
                 : "+f"(d[0]), "+f"(d[1]), "+f"(d[2]), "+f"(d[3])
                 : "r"(a0), "r"(a1), "r"(a2), "r"(a3), "r"(b0), "r"(b1));
}
__device__ __forceinline__ void hilo_pack(float r0, float r1, uint32_t& h, uint32_t& l) {
    h = bf16x2_of(r1, r0);
    float hi0 = __uint_as_float(h << 16);
    float hi1 = __uint_as_float(h & 0xFFFF0000u);
    l = bf16x2_of(r1 - hi1, r0 - hi0);
}
__device__ __forceinline__ void cpasync16(uint32_t dst, const void* src, int srcsize) {
    asm volatile("cp.async.ca.shared.global [%0], [%1], 16, %2;"
                 :: "r"(dst), "l"(src), "r"(srcsize) : "memory");
}
__device__ __forceinline__ void cpcommit() { asm volatile("cp.async.commit_group;" ::: "memory"); }
__device__ __forceinline__ void cpwait0()  { asm volatile("cp.async.wait_group 0;" ::: "memory"); }

// ---------------- kernel 1: NCHW -> NHWC (f32 + bf16 hi/lo) ----------------
__global__ void __launch_bounds__(256) k_transpose(const float* __restrict__ x) {
    __shared__ float sh[64][33];
    int blk = blockIdx.x;
    int b   = blk >> 9;
    int hw0 = (blk & 511) << 5;
    int t = threadIdx.x;
#pragma unroll
    for (int i = 0; i < 8; i++) {
        int e = t + i * 256;
        int c = e >> 5, wp = e & 31;
        sh[c][wp] = x[((size_t)(b * 64 + c) << 14) + hw0 + wp];
    }
    __syncthreads();
#pragma unroll
    for (int i = 0; i < 8; i++) {
        int e = t + i * 256;
        int wp = e >> 6, c = e & 63;
        float v = sh[c][wp];
        size_t idx = (((size_t)b << 14) + hw0 + wp) * 64 + c;
        g_xt[idx] = v;
        __nv_bfloat16 hb = __float2bfloat16(v);
        g_xh[idx] = hb;
        g_xl[idx] = __float2bfloat16(v - __bfloat162float(hb));
    }
}

// ---------------- kernel 2a: pack w_conv (deform B tiles, 64x64) ----------------
__global__ void k_wpack(const float* __restrict__ w_conv) {
    int t = blockIdx.x * 256 + threadIdx.x;
    if (t >= 9 * 4096) return;
    int tap = t >> 12;
    int r   = t & 4095;
    int o = r >> 6, c = r & 63;
    float w = w_conv[o * 576 + c * 9 + tap];
    __nv_bfloat16 hb = __float2bfloat16(w);
    __nv_bfloat16 lb = __float2bfloat16(w - __bfloat162float(hb));
    uint32_t swo = sw128(o * 128 + c * 2);
    char* base = (char*)g_wqs + tap * 16384;
    *(__nv_bfloat16*)(base + swo)        = hb;
    *(__nv_bfloat16*)(base + 8192 + swo) = lb;
}

// ---------------- kernel 2b: pack w_offset/w_mask (conv B tiles, 32x64) ----------------
__global__ void k_wpack2(const float* __restrict__ w_off, const float* __restrict__ w_msk) {
    int t = blockIdx.x * 256 + threadIdx.x;
    if (t >= 9 * 2048) return;
    int tap = t >> 11;
    int r   = t & 2047;
    int o = r >> 6, c = r & 63;
    float w = 0.f;
    if (o < 18)      w = w_off[o * 576 + c * 9 + tap];
    else if (o < 27) w = w_msk[(o - 18) * 576 + c * 9 + tap];
    __nv_bfloat16 hb = __float2bfloat16(w);
    __nv_bfloat16 lb = __float2bfloat16(w - __bfloat162float(hb));
    uint32_t swo = sw128(o * 128 + c * 2);
    char* base = (char*)g_wom + tap * 8192;
    *(__nv_bfloat16*)(base + swo)        = hb;
    *(__nv_bfloat16*)(base + 4096 + swo) = lb;
}

// ---------------- kernel 3: offset+mask conv via MMA, row-grouped A staging ----------------
// Tap order dy-major: group g (=dy) covers taps 3g..3g+2. One 130-slot halo row
// (hi+lo) per group, double-buffered; dx handled by shifted ldmatrix slot.
// Row buffer: part stride 17408B; buffer = 2 parts = 34816B. Rows at 0, B at 69632.
#define CR(s)  ((s) * 34816)
#define CBB(s) (69632 + (s) * 8192)
#define CONV_SMEM 86016
__global__ void __launch_bounds__(256) k_conv() {
    extern __shared__ __align__(1024) char smem[];
    uint32_t sb = smem_u32(smem);

    int t = threadIdx.x, warp = t >> 5, lane = t & 31;
    int h = blockIdx.x & 127;
    int b = blockIdx.x >> 7;
    const __nv_bfloat16* xh = g_xh + ((size_t)b << 20);
    const __nv_bfloat16* xl = g_xl + ((size_t)b << 20);

    float d[4][4];
#pragma unroll
    for (int nb = 0; nb < 4; nb++)
#pragma unroll
        for (int i = 0; i < 4; i++) d[nb][i] = 0.f;

    int a_row = warp * 16 + (lane & 7) + ((lane >> 3) & 1) * 8;
    int a_kx  = ((lane >> 4) & 1) * 16;
    int b_row2 = ((lane >> 4) & 1) * 8 + (lane & 7);
    int b_kx2  = ((lane >> 3) & 1) * 16;

    // copy halo row (hh = h-1+dy): 130 slots x 8 units x 2 parts = 2080 cp.async
    auto copyRow = [&](int dy, int s) {
        int hh = h - 1 + dy;
        bool okh = (unsigned)hh < 128u;
        const __nv_bfloat16* rh = xh + ((size_t)(hh & 127) << 13);
        const __nv_bfloat16* rl = xl + ((size_t)(hh & 127) << 13);
        uint32_t dR = sb + CR(s);
        for (int i = t; i < 2080; i += 256) {
            int part = (i >= 1040) ? 1 : 0;
            int r = i - part * 1040;
            int slot = r >> 3, u = r & 7;
            int gx = slot - 1;
            bool ok = okh && ((unsigned)gx < 128u);
            const __nv_bfloat16* src = (part ? rl : rh) + ((gx & 127) << 6) + u * 8;
            uint32_t dst = dR + part * 17408 + sw128((uint32_t)(slot * 128 + u * 16));
            cpasync16(dst, src, ok ? 16 : 0);
        }
    };
    auto copyB = [&](int tap, int s) {
        const char* src = (const char*)g_wom + tap * 8192;
        uint32_t dB = sb + CBB(s);
#pragma unroll
        for (int i = 0; i < 2; i++) {
            int u = i * 256 + t;
            cpasync16(dB + u * 16, src + u * 16, 16);
        }
    };

    copyRow(0, 0); copyB(0, 0); cpcommit(); cpwait0();
    __syncthreads();

#pragma unroll 1
    for (int tap = 0; tap < 9; tap++) {
        int dy = tap / 3, sx = tap - dy * 3;
        int sB = tap & 1;
        // schedule next copies: B every tap; row at group starts (taps 0 and 3)
        if (tap < 8) copyB(tap + 1, sB ^ 1);
        if (tap == 0) copyRow(1, 1);
        if (tap == 3) copyRow(2, 0);
        if (tap < 8) cpcommit();

        uint32_t hiB = sb + CR(dy & 1), loB = hiB + 17408, bB = sb + CBB(sB);
#pragma unroll
        for (int kb = 0; kb < 4; kb++) {
            uint32_t aoff = sw128((uint32_t)((a_row + sx) * 128 + kb * 32 + a_kx));
            uint32_t ah0, ah1, ah2, ah3, al0, al1, al2, al3;
            ldsm4(hiB + aoff, ah0, ah1, ah2, ah3);
            ldsm4(loB + aoff, al0, al1, al2, al3);
#pragma unroll
            for (int nbp = 0; nbp < 2; nbp++) {
                uint32_t boff = sw128((uint32_t)((nbp * 16 + b_row2) * 128 + kb * 32 + b_kx2));
                uint32_t bh0, bh1, bh2, bh3, bl0, bl1, bl2, bl3;
                ldsm4(bB + boff, bh0, bh1, bh2, bh3);
                ldsm4(bB + 4096 + boff, bl0, bl1, bl2, bl3);
                mma16816(d[nbp * 2],     ah0, ah1, ah2, ah3, bh0, bh1);
                mma16816(d[nbp * 2],     ah0, ah1, ah2, ah3, bl0, bl1);
                mma16816(d[nbp * 2],     al0, al1, al2, al3, bh0, bh1);
                mma16816(d[nbp * 2 + 1], ah0, ah1, ah2, ah3, bh2, bh3);
                mma16816(d[nbp * 2 + 1], ah0, ah1, ah2, ah3, bl2, bl3);
                mma16816(d[nbp * 2 + 1], al0, al1, al2, al3, bh2, bh3);
            }
        }
        cpwait0();
        __syncthreads();
    }

    // transpose D through smem: sD[px][33]
    float* sD = (float*)smem;
    {
        int r0 = warp * 16 + (lane >> 2);
        int r1 = r0 + 8;
#pragma unroll
        for (int nb = 0; nb < 4; nb++) {
            int o0 = nb * 8 + (lane & 3) * 2;
            sD[r0 * 33 + o0]     = d[nb][0];
            sD[r0 * 33 + o0 + 1] = d[nb][1];
            sD[r1 * 33 + o0]     = d[nb][2];
            sD[r1 * 33 + o0 + 1] = d[nb][3];
        }
    }
    __syncthreads();

    if (t < 128) {
        int w = t;
        const float* rr = sD + t * 33;
        int p = b * 16384 + h * 128 + w;
#pragma unroll
        for (int k = 0; k < 9; k++) {
            float oy = rr[2 * k], ox = rr[2 * k + 1];
            float m  = 1.f / (1.f + __expf(-rr[18 + k]));
            float py = (float)(h + k / 3 - 1) + oy;
            float px = (float)(w + k % 3 - 1) + ox;
            float y0f = floorf(py), x0f = floorf(px);
            float wy1 = py - y0f, wy0 = 1.f - wy1;
            float wx1 = px - x0f, wx0 = 1.f - wx1;
            int y0 = (int)y0f, x0i = (int)x0f;
            int y1 = y0 + 1, x1i = x0i + 1;
            bool vy0 = (unsigned)y0  < 128u, vy1 = (unsigned)y1  < 128u;
            bool vx0 = (unsigned)x0i < 128u, vx1 = (unsigned)x1i < 128u;
            int cy0 = min(max(y0, 0), 127), cy1 = min(max(y1, 0), 127);
            int cx0 = min(max(x0i, 0), 127), cx1 = min(max(x1i, 0), 127);
            int4 ci; float4 cw;
            ci.x = cy0 * 128 + cx0; cw.x = (vy0 && vx0) ? m * wy0 * wx0 : 0.f;
            ci.y = cy0 * 128 + cx1; cw.y = (vy0 && vx1) ? m * wy0 * wx1 : 0.f;
            ci.z = cy1 * 128 + cx0; cw.z = (vy1 && vx0) ? m * wy1 * wx0 : 0.f;
            ci.w = cy1 * 128 + cx1; cw.w = (vy1 && vx1) ? m * wy1 * wx1 : 0.f;
            g_ci2[(size_t)k * NPIX + p] = ci;
            g_cw2[(size_t)k * NPIX + p] = cw;
        }
    }
}

// ---------------- kernel 4: deform gather + mma, register-staged pipeline (R10 exact) ----------------
#define D_A(s)  ((s) * 32768)
#define D_B(s)  (65536 + (s) * 16384)
#define D_CI(s) (98304 + (s) * 4096)
#define DEF_SMEM 106496
__global__ void __launch_bounds__(256, 2) k_deform(float* __restrict__ out) {
    extern __shared__ __align__(1024) char smem[];
    uint32_t sb = smem_u32(smem);

    int t = threadIdx.x, warp = t >> 5, lane = t & 31;
    int P0 = blockIdx.x << 7;
    int b = P0 >> 14, hwbase = P0 & 16383;
    const float* xb = g_xt + ((size_t)b << 20);

    float d[8][4];
#pragma unroll
    for (int nb = 0; nb < 8; nb++)
#pragma unroll
        for (int i = 0; i < 4; i++) d[nb][i] = 0.f;

    int a_row = warp * 16 + (lane & 7) + ((lane >> 3) & 1) * 8;
    int a_kx  = ((lane >> 4) & 1) * 16;
    int b_row2 = ((lane >> 4) & 1) * 8 + (lane & 7);
    int b_kx2  = ((lane >> 3) & 1) * 16;

    auto prefetchCI = [&](int tap, int s) {
        uint32_t dst = sb + D_CI(s);
        if (t < 128) cpasync16(dst + t * 16, g_ci2 + (size_t)tap * NPIX + P0 + t, 16);
        else         cpasync16(dst + 2048 + (t - 128) * 16, g_cw2 + (size_t)tap * NPIX + P0 + (t - 128), 16);
    };
    auto copyB = [&](int tap, int s) {
        const char* src = (const char*)g_wqs + tap * 16384;
        uint32_t dB = sb + D_B(s);
#pragma unroll
        for (int i = 0; i < 4; i++) {
            int u = i * 256 + t;
            cpasync16(dB + u * 16, src + u * 16, 16);
        }
    };

    float4 vv[2][4]; float4 cwq[2]; uint32_t swoq[2];
    auto issue2 = [&](int ciS, int it0) {
        const int4*   sCI = (const int4*)(smem + D_CI(ciS));
        const float4* sCW = (const float4*)(smem + D_CI(ciS) + 2048);
#pragma unroll
        for (int q = 0; q < 2; q++) {
            int i = ((it0 + q) << 8) + t;
            int px = i >> 4, cg = i & 15;
            int4 ci = sCI[px];
            cwq[q]  = sCW[px];
            vv[q][0] = *((const float4*)(xb + ((size_t)ci.x << 6)) + cg);
            vv[q][1] = *((const float4*)(xb + ((size_t)ci.y << 6)) + cg);
            vv[q][2] = *((const float4*)(xb + ((size_t)ci.z << 6)) + cg);
            vv[q][3] = *((const float4*)(xb + ((size_t)ci.w << 6)) + cg);
            swoq[q] = sw128((uint32_t)(px * 128 + cg * 8));
        }
    };
    auto flush2 = [&](uint32_t dA) {
#pragma unroll
        for (int q = 0; q < 2; q++) {
            float4 cw = cwq[q];
            float r0 = cw.x * vv[q][0].x + cw.y * vv[q][1].x + cw.z * vv[q][2].x + cw.w * vv[q][3].x;
            float r1 = cw.x * vv[q][0].y + cw.y * vv[q][1].y + cw.z * vv[q][2].y + cw.w * vv[q][3].y;
            float r2 = cw.x * vv[q][0].z + cw.y * vv[q][1].z + cw.z * vv[q][2].z + cw.w * vv[q][3].z;
            float r3 = cw.x * vv[q][0].w + cw.y * vv[q][1].w + cw.z * vv[q][2].w + cw.w * vv[q][3].w;
            uint32_t h01, l01, h23, l23;
            hilo_pack(r0, r1, h01, l01);
            hilo_pack(r2, r3, h23, l23);
            sts64(dA + swoq[q], h01, h23);
            sts64(dA + 16384 + swoq[q], l01, l23);
        }
    };
    auto do_kb = [&](int kb, uint32_t aB, uint32_t bB) {
        uint32_t aoff = sw128((uint32_t)(a_row * 128 + kb * 32 + a_kx));
        uint32_t ah0, ah1, ah2, ah3, al0, al1, al2, al3;
        ldsm4(aB + aoff, ah0, ah1, ah2, ah3);
        ldsm4(aB + 16384 + aoff, al0, al1, al2, al3);
#pragma unroll
        for (int nbp = 0; nbp < 4; nbp++) {
            uint32_t boff = sw128((uint32_t)((nbp * 16 + b_row2) * 128 + kb * 32 + b_kx2));
            uint32_t bh0, bh1, bh2, bh3, bl0, bl1, bl2, bl3;
            ldsm4(bB + boff, bh0, bh1, bh2, bh3);
            ldsm4(bB + 8192 + boff, bl0, bl1, bl2, bl3);
            mma16816(d[nbp * 2],     ah0, ah1, ah2, ah3, bh0, bh1);
            mma16816(d[nbp * 2],     ah0, ah1, ah2, ah3, bl0, bl1);
            mma16816(d[nbp * 2],     al0, al1, al2, al3, bh0, bh1);
            mma16816(d[nbp * 2 + 1], ah0, ah1, ah2, ah3, bh2, bh3);
            mma16816(d[nbp * 2 + 1], ah0, ah1, ah2, ah3, bl2, bl3);
            mma16816(d[nbp * 2 + 1], al0, al1, al2, al3, bh2, bh3);
        }
    };

    // ---- prologue ----
    prefetchCI(0, 0); copyB(0, 0); cpcommit(); cpwait0();
    __syncthreads();
    {
        const int4*   sCI = (const int4*)(smem + D_CI(0));
        const float4* sCW = (const float4*)(smem + D_CI(0) + 2048);
        uint32_t dA = sb + D_A(0);
#pragma unroll 2
        for (int it = 0; it < 8; it++) {
            int i = (it << 8) + t;
            int px = i >> 4, cg = i & 15;
            int4 ci = sCI[px];
            float4 cw = sCW[px];
            float4 v0 = *((const float4*)(xb + ((size_t)ci.x << 6)) + cg);
            float4 v1 = *((const float4*)(xb + ((size_t)ci.y << 6)) + cg);
            float4 v2 = *((const float4*)(xb + ((size_t)ci.z << 6)) + cg);
            float4 v3 = *((const float4*)(xb + ((size_t)ci.w << 6)) + cg);
            float r0 = cw.x * v0.x + cw.y * v1.x + cw.z * v2.x + cw.w * v3.x;
            float r1 = cw.x * v0.y + cw.y * v1.y + cw.z * v2.y + cw.w * v3.y;
            float r2 = cw.x * v0.z + cw.y * v1.z + cw.z * v2.z + cw.w * v3.z;
            float r3 = cw.x * v0.w + cw.y * v1.w + cw.z * v2.w + cw.w * v3.w;
            uint32_t h01, l01, h23, l23;
            hilo_pack(r0, r1, h01, l01);
            hilo_pack(r2, r3, h23, l23);
            uint32_t swo = sw128((uint32_t)(px * 128 + cg * 8));
            sts64(dA + swo, h01, h23);
            sts64(dA + 16384 + swo, l01, l23);
        }
    }
    prefetchCI(1, 1); cpcommit(); cpwait0();
    __syncthreads();

    // ---- main loop ----
#pragma unroll 1
    for (int tap = 0; tap < 9; tap++) {
        int s = tap & 1;
        uint32_t aB = sb + D_A(s), bB = sb + D_B(s);
        if (tap < 8) {
            copyB(tap + 1, s ^ 1);
            if (tap + 2 <= 8) prefetchCI(tap + 2, s);
            cpcommit();
        }
        uint32_t dA = sb + D_A(s ^ 1);
        if (tap < 8) issue2(s ^ 1, 0);
        do_kb(0, aB, bB);
        if (tap < 8) { flush2(dA); issue2(s ^ 1, 2); }
        do_kb(1, aB, bB);
        if (tap < 8) { flush2(dA); issue2(s ^ 1, 4); }
        do_kb(2, aB, bB);
        if (tap < 8) { flush2(dA); issue2(s ^ 1, 6); }
        do_kb(3, aB, bB);
        if (tap < 8) flush2(dA);
        cpwait0();
        __syncthreads();
    }

    // epilogue
    size_t bo = (size_t)b << 20;
    int r0 = hwbase + warp * 16 + (lane >> 2);
    int r1 = r0 + 8;
#pragma unroll
    for (int nb = 0; nb < 8; nb++) {
        int o0 = nb * 8 + (lane & 3) * 2;
        out[bo + (size_t)o0 * 16384 + r0]       = d[nb][0];
        out[bo + (size_t)(o0 + 1) * 16384 + r0] = d[nb][1];
        out[bo + (size_t)o0 * 16384 + r1]       = d[nb][2];
        out[bo + (size_t)(o0 + 1) * 16384 + r1] = d[nb][3];
    }
}

// ---------------- launch ----------------
extern "C" void kernel_launch(void* const* d_in, const int* in_sizes, int n_in,
                              void* d_out, int out_size) {
    (void)in_sizes; (void)n_in; (void)out_size;
    const float* x      = (const float*)d_in[0];
    const float* w_conv = (const float*)d_in[1];
    const float* w_off  = (const float*)d_in[2];
    const float* w_msk  = (const float*)d_in[3];
    float* out = (float*)d_out;

    cudaFuncSetAttribute(k_conv,   cudaFuncAttributeMaxDynamicSharedMemorySize, CONV_SMEM);
    cudaFuncSetAttribute(k_deform, cudaFuncAttributeMaxDynamicSharedMemorySize, DEF_SMEM);

    k_transpose<<<4096, 256>>>(x);
    k_wpack<<<(9 * 4096 + 255) / 256, 256>>>(w_conv);
    k_wpack2<<<(9 * 2048 + 255) / 256, 256>>>(w_off, w_msk);
    k_conv<<<1024, 256, CONV_SMEM>>>();
    k_deform<<<1024, 256, DEF_SMEM>>>(out);
}

// round 13
// speedup vs baseline: 1.7752x; 1.0641x over previous
#include <cuda_runtime.h>
#include <cuda_bf16.h>
#include <cstdint>

#define HWsz 16384
#define NPIX (8 * HWsz)   // 131072 pixels

// -------- scratch --------
__device__ float            g_xt[(size_t)NPIX * 64];    // NHWC x (f32, for deform bilinear blend)
__device__ __nv_bfloat16    g_xh[(size_t)NPIX * 64];    // NHWC x bf16 hi
__device__ __nv_bfloat16    g_xl[(size_t)NPIX * 64];    // NHWC x bf16 lo
__device__ __align__(16) uint32_t g_wqs[9 * 4096];      // deform W: per tap 16KB (hi 8KB + lo 8KB), 64x64 bf16 SW128
__device__ __align__(16) uint32_t g_wom[9 * 2048];      // conv W: per tap 8KB (hi 4KB + lo 4KB), 32x64 bf16 SW128
__device__ int4   g_ci2[(size_t)9 * NPIX];              // corner indices, [tap][pixel]
__device__ float4 g_cw2[(size_t)9 * NPIX];              // corner weights, [tap][pixel]

// -------- helpers --------
__device__ __forceinline__ uint32_t smem_u32(const void* p) {
    return (uint32_t)__cvta_generic_to_shared(p);
}
__device__ __forceinline__ void sts64(uint32_t addr, uint32_t a, uint32_t b) {
    asm volatile("st.shared.v2.b32 [%0], {%1, %2};" :: "r"(addr), "r"(a), "r"(b) : "memory");
}
__device__ __forceinline__ uint32_t bf16x2_of(float hi, float lo) {
    uint32_t r; asm("cvt.rn.bf16x2.f32 %0, %1, %2;" : "=r"(r) : "f"(hi), "f"(lo)); return r;
}
__device__ __forceinline__ uint32_t sw128(uint32_t off) { return off ^ ((off >> 3) & 0x70); }

__device__ __forceinline__ void ldsm4(uint32_t addr, uint32_t& r0, uint32_t& r1, uint32_t& r2, uint32_t& r3) {
    asm volatile("ldmatrix.sync.aligned.m8n8.x4.shared.b16 {%0,%1,%2,%3}, [%4];"
                 : "=r"(r0), "=r"(r1), "=r"(r2), "=r"(r3) : "r"(addr));
}
__device__ __forceinline__ void mma16816(float* d, uint32_t a0, uint32_t a1, uint32_t a2, uint32_t a3,
                                         uint32_t b0, uint32_t b1) {
    asm volatile("mma.sync.aligned.m16n8k16.row.col.f32.bf16.bf16.f32 "
                 "{%0,%1,%2,%3}, {%4,%5,%6,%7}, {%8,%9}, {%0,%1,%2,%3};"
                 : "+f"(d[0]), "+f"(d[1]), "+f"(d[2]), "+f"(d[3])
                 : "r"(a0), "r"(a1), "r"(a2), "r"(a3), "r"(b0), "r"(b1));
}
__device__ __forceinline__ void hilo_pack(float r0, float r1, uint32_t& h, uint32_t& l) {
    h = bf16x2_of(r1, r0);
    float hi0 = __uint_as_float(h << 16);
    float hi1 = __uint_as_float(h & 0xFFFF0000u);
    l = bf16x2_of(r1 - hi1, r0 - hi0);
}
__device__ __forceinline__ void cpasync16(uint32_t dst, const void* src, int srcsize) {
    asm volatile("cp.async.ca.shared.global [%0], [%1], 16, %2;"
                 :: "r"(dst), "l"(src), "r"(srcsize) : "memory");
}
__device__ __forceinline__ void cpcommit() { asm volatile("cp.async.commit_group;" ::: "memory"); }
__device__ __forceinline__ void cpwait0()  { asm volatile("cp.async.wait_group 0;" ::: "memory"); }

// ---------------- kernel 1: fused prep (transpose + both weight packs) ----------------
__global__ void __launch_bounds__(256) k_prep(const float* __restrict__ x,
                                              const float* __restrict__ w_conv,
                                              const float* __restrict__ w_off,
                                              const float* __restrict__ w_msk) {
    __shared__ float sh[64][33];
    int blk = blockIdx.x;
    int tid = threadIdx.x;
    if (blk < 4096) {
        // NCHW -> NHWC (f32 + bf16 hi/lo)
        int b   = blk >> 9;
        int hw0 = (blk & 511) << 5;
#pragma unroll
        for (int i = 0; i < 8; i++) {
            int e = tid + i * 256;
            int c = e >> 5, wp = e & 31;
            sh[c][wp] = x[((size_t)(b * 64 + c) << 14) + hw0 + wp];
        }
        __syncthreads();
#pragma unroll
        for (int i = 0; i < 8; i++) {
            int e = tid + i * 256;
            int wp = e >> 6, c = e & 63;
            float v = sh[c][wp];
            size_t idx = (((size_t)b << 14) + hw0 + wp) * 64 + c;
            g_xt[idx] = v;
            __nv_bfloat16 hb = __float2bfloat16(v);
            g_xh[idx] = hb;
            g_xl[idx] = __float2bfloat16(v - __bfloat162float(hb));
        }
    } else if (blk < 4096 + 144) {
        // pack w_conv (deform B tiles, 64x64)
        int t = (blk - 4096) * 256 + tid;   // < 36864
        int tap = t >> 12;
        int r   = t & 4095;
        int o = r >> 6, c = r & 63;
        float w = w_conv[o * 576 + c * 9 + tap];
        __nv_bfloat16 hb = __float2bfloat16(w);
        __nv_bfloat16 lb = __float2bfloat16(w - __bfloat162float(hb));
        uint32_t swo = sw128(o * 128 + c * 2);
        char* base = (char*)g_wqs + tap * 16384;
        *(__nv_bfloat16*)(base + swo)        = hb;
        *(__nv_bfloat16*)(base + 8192 + swo) = lb;
    } else {
        // pack w_offset/w_mask (conv B tiles, 32x64)
        int t = (blk - 4240) * 256 + tid;   // < 18432
        int tap = t >> 11;
        int r   = t & 2047;
        int o = r >> 6, c = r & 63;
        float w = 0.f;
        if (o < 18)      w = w_off[o * 576 + c * 9 + tap];
        else if (o < 27) w = w_msk[(o - 18) * 576 + c * 9 + tap];
        __nv_bfloat16 hb = __float2bfloat16(w);
        __nv_bfloat16 lb = __float2bfloat16(w - __bfloat162float(hb));
        uint32_t swo = sw128(o * 128 + c * 2);
        char* base = (char*)g_wom + tap * 8192;
        *(__nv_bfloat16*)(base + swo)        = hb;
        *(__nv_bfloat16*)(base + 4096 + swo) = lb;
    }
}

// ---------------- kernel 2: offset+mask conv via MMA, row-grouped A staging (R12) ----------------
#define CR(s)  ((s) * 34816)
#define CBB(s) (69632 + (s) * 8192)
#define CONV_SMEM 86016
__global__ void __launch_bounds__(256) k_conv() {
    extern __shared__ __align__(1024) char smem[];
    uint32_t sb = smem_u32(smem);

    int t = threadIdx.x, warp = t >> 5, lane = t & 31;
    int h = blockIdx.x & 127;
    int b = blockIdx.x >> 7;
    const __nv_bfloat16* xh = g_xh + ((size_t)b << 20);
    const __nv_bfloat16* xl = g_xl + ((size_t)b << 20);

    float d[4][4];
#pragma unroll
    for (int nb = 0; nb < 4; nb++)
#pragma unroll
        for (int i = 0; i < 4; i++) d[nb][i] = 0.f;

    int a_row = warp * 16 + (lane & 7) + ((lane >> 3) & 1) * 8;
    int a_kx  = ((lane >> 4) & 1) * 16;
    int b_row2 = ((lane >> 4) & 1) * 8 + (lane & 7);
    int b_kx2  = ((lane >> 3) & 1) * 16;

    auto copyRow = [&](int dy, int s) {
        int hh = h - 1 + dy;
        bool okh = (unsigned)hh < 128u;
        const __nv_bfloat16* rh = xh + ((size_t)(hh & 127) << 13);
        const __nv_bfloat16* rl = xl + ((size_t)(hh & 127) << 13);
        uint32_t dR = sb + CR(s);
        for (int i = t; i < 2080; i += 256) {
            int part = (i >= 1040) ? 1 : 0;
            int r = i - part * 1040;
            int slot = r >> 3, u = r & 7;
            int gx = slot - 1;
            bool ok = okh && ((unsigned)gx < 128u);
            const __nv_bfloat16* src = (part ? rl : rh) + ((gx & 127) << 6) + u * 8;
            uint32_t dst = dR + part * 17408 + sw128((uint32_t)(slot * 128 + u * 16));
            cpasync16(dst, src, ok ? 16 : 0);
        }
    };
    auto copyB = [&](int tap, int s) {
        const char* src = (const char*)g_wom + tap * 8192;
        uint32_t dB = sb + CBB(s);
#pragma unroll
        for (int i = 0; i < 2; i++) {
            int u = i * 256 + t;
            cpasync16(dB + u * 16, src + u * 16, 16);
        }
    };

    copyRow(0, 0); copyB(0, 0); cpcommit(); cpwait0();
    __syncthreads();

#pragma unroll 1
    for (int tap = 0; tap < 9; tap++) {
        int dy = tap / 3, sx = tap - dy * 3;
        int sB = tap & 1;
        if (tap < 8) copyB(tap + 1, sB ^ 1);
        if (tap == 0) copyRow(1, 1);
        if (tap == 3) copyRow(2, 0);
        if (tap < 8) cpcommit();

        uint32_t hiB = sb + CR(dy & 1), loB = hiB + 17408, bB = sb + CBB(sB);
#pragma unroll
        for (int kb = 0; kb < 4; kb++) {
            uint32_t aoff = sw128((uint32_t)((a_row + sx) * 128 + kb * 32 + a_kx));
            uint32_t ah0, ah1, ah2, ah3, al0, al1, al2, al3;
            ldsm4(hiB + aoff, ah0, ah1, ah2, ah3);
            ldsm4(loB + aoff, al0, al1, al2, al3);
#pragma unroll
            for (int nbp = 0; nbp < 2; nbp++) {
                uint32_t boff = sw128((uint32_t)((nbp * 16 + b_row2) * 128 + kb * 32 + b_kx2));
                uint32_t bh0, bh1, bh2, bh3, bl0, bl1, bl2, bl3;
                ldsm4(bB + boff, bh0, bh1, bh2, bh3);
                ldsm4(bB + 4096 + boff, bl0, bl1, bl2, bl3);
                mma16816(d[nbp * 2],     ah0, ah1, ah2, ah3, bh0, bh1);
                mma16816(d[nbp * 2],     ah0, ah1, ah2, ah3, bl0, bl1);
                mma16816(d[nbp * 2],     al0, al1, al2, al3, bh0, bh1);
                mma16816(d[nbp * 2 + 1], ah0, ah1, ah2, ah3, bh2, bh3);
                mma16816(d[nbp * 2 + 1], ah0, ah1, ah2, ah3, bl2, bl3);
                mma16816(d[nbp * 2 + 1], al0, al1, al2, al3, bh2, bh3);
            }
        }
        cpwait0();
        __syncthreads();
    }

    // transpose D through smem: sD[px][33]
    float* sD = (float*)smem;
    {
        int r0 = warp * 16 + (lane >> 2);
        int r1 = r0 + 8;
#pragma unroll
        for (int nb = 0; nb < 4; nb++) {
            int o0 = nb * 8 + (lane & 3) * 2;
            sD[r0 * 33 + o0]     = d[nb][0];
            sD[r0 * 33 + o0 + 1] = d[nb][1];
            sD[r1 * 33 + o0]     = d[nb][2];
            sD[r1 * 33 + o0 + 1] = d[nb][3];
        }
    }
    __syncthreads();

    if (t < 128) {
        int w = t;
        const float* rr = sD + t * 33;
        int p = b * 16384 + h * 128 + w;
#pragma unroll
        for (int k = 0; k < 9; k++) {
            float oy = rr[2 * k], ox = rr[2 * k + 1];
            float m  = 1.f / (1.f + __expf(-rr[18 + k]));
            float py = (float)(h + k / 3 - 1) + oy;
            float px = (float)(w + k % 3 - 1) + ox;
            float y0f = floorf(py), x0f = floorf(px);
            float wy1 = py - y0f, wy0 = 1.f - wy1;
            float wx1 = px - x0f, wx0 = 1.f - wx1;
            int y0 = (int)y0f, x0i = (int)x0f;
            int y1 = y0 + 1, x1i = x0i + 1;
            bool vy0 = (unsigned)y0  < 128u, vy1 = (unsigned)y1  < 128u;
            bool vx0 = (unsigned)x0i < 128u, vx1 = (unsigned)x1i < 128u;
            int cy0 = min(max(y0, 0), 127), cy1 = min(max(y1, 0), 127);
            int cx0 = min(max(x0i, 0), 127), cx1 = min(max(x1i, 0), 127);
            int4 ci; float4 cw;
            ci.x = cy0 * 128 + cx0; cw.x = (vy0 && vx0) ? m * wy0 * wx0 : 0.f;
            ci.y = cy0 * 128 + cx1; cw.y = (vy0 && vx1) ? m * wy0 * wx1 : 0.f;
            ci.z = cy1 * 128 + cx0; cw.z = (vy1 && vx0) ? m * wy1 * wx0 : 0.f;
            ci.w = cy1 * 128 + cx1; cw.w = (vy1 && vx1) ? m * wy1 * wx1 : 0.f;
            g_ci2[(size_t)k * NPIX + p] = ci;
            g_cw2[(size_t)k * NPIX + p] = cw;
        }
    }
}

// ---------------- kernel 3: deform gather + mma, 32px x 32o warp tiles ----------------
#define D_A(s)  ((s) * 32768)
#define D_B(s)  (65536 + (s) * 16384)
#define D_CI(s) (98304 + (s) * 4096)
#define DEF_SMEM 106496
__global__ void __launch_bounds__(256, 2) k_deform(float* __restrict__ out) {
    extern __shared__ __align__(1024) char smem[];
    uint32_t sb = smem_u32(smem);

    int t = threadIdx.x, warp = t >> 5, lane = t & 31;
    int P0 = blockIdx.x << 7;
    int b = P0 >> 14, hwbase = P0 & 16383;
    const float* xb = g_xt + ((size_t)b << 20);

    // warp tile: 32 px x 32 o.  pxb = warp&3 (px block), ob = warp>>2 (o block)
    int pxb = warp & 3, ob = warp >> 2;
    int a_row0 = pxb * 32 + (lane & 7) + ((lane >> 3) & 1) * 8;   // + mt*16
    int a_kx   = ((lane >> 4) & 1) * 16;
    int b_row2 = ((lane >> 4) & 1) * 8 + (lane & 7);
    int b_kx2  = ((lane >> 3) & 1) * 16;

    float d[2][4][4];   // [m-tile][n8-tile][frag]
#pragma unroll
    for (int mt = 0; mt < 2; mt++)
#pragma unroll
        for (int nb = 0; nb < 4; nb++)
#pragma unroll
            for (int i = 0; i < 4; i++) d[mt][nb][i] = 0.f;

    auto prefetchCI = [&](int tap, int s) {
        uint32_t dst = sb + D_CI(s);
        if (t < 128) cpasync16(dst + t * 16, g_ci2 + (size_t)tap * NPIX + P0 + t, 16);
        else         cpasync16(dst + 2048 + (t - 128) * 16, g_cw2 + (size_t)tap * NPIX + P0 + (t - 128), 16);
    };
    auto copyB = [&](int tap, int s) {
        const char* src = (const char*)g_wqs + tap * 16384;
        uint32_t dB = sb + D_B(s);
#pragma unroll
        for (int i = 0; i < 4; i++) {
            int u = i * 256 + t;
            cpasync16(dB + u * 16, src + u * 16, 16);
        }
    };

    float4 vv[2][4]; float4 cwq[2]; uint32_t swoq[2];
    auto issue2 = [&](int ciS, int it0) {
        const int4*   sCI = (const int4*)(smem + D_CI(ciS));
        const float4* sCW = (const float4*)(smem + D_CI(ciS) + 2048);
#pragma unroll
        for (int q = 0; q < 2; q++) {
            int i = ((it0 + q) << 8) + t;
            int px = i >> 4, cg = i & 15;
            int4 ci = sCI[px];
            cwq[q]  = sCW[px];
            vv[q][0] = *((const float4*)(xb + ((size_t)ci.x << 6)) + cg);
            vv[q][1] = *((const float4*)(xb + ((size_t)ci.y << 6)) + cg);
            vv[q][2] = *((const float4*)(xb + ((size_t)ci.z << 6)) + cg);
            vv[q][3] = *((const float4*)(xb + ((size_t)ci.w << 6)) + cg);
            swoq[q] = sw128((uint32_t)(px * 128 + cg * 8));
        }
    };
    auto flush2 = [&](uint32_t dA) {
#pragma unroll
        for (int q = 0; q < 2; q++) {
            float4 cw = cwq[q];
            float r0 = cw.x * vv[q][0].x + cw.y * vv[q][1].x + cw.z * vv[q][2].x + cw.w * vv[q][3].x;
            float r1 = cw.x * vv[q][0].y + cw.y * vv[q][1].y + cw.z * vv[q][2].y + cw.w * vv[q][3].y;
            float r2 = cw.x * vv[q][0].z + cw.y * vv[q][1].z + cw.z * vv[q][2].z + cw.w * vv[q][3].z;
            float r3 = cw.x * vv[q][0].w + cw.y * vv[q][1].w + cw.z * vv[q][2].w + cw.w * vv[q][3].w;
            uint32_t h01, l01, h23, l23;
            hilo_pack(r0, r1, h01, l01);
            hilo_pack(r2, r3, h23, l23);
            sts64(dA + swoq[q], h01, h23);
            sts64(dA + 16384 + swoq[q], l01, l23);
        }
    };
    auto do_kb = [&](int kb, uint32_t aB, uint32_t bB) {
        uint32_t ah[2][4], al[2][4];
#pragma unroll
        for (int mt = 0; mt < 2; mt++) {
            uint32_t aoff = sw128((uint32_t)((a_row0 + mt * 16) * 128 + kb * 32 + a_kx));
            ldsm4(aB + aoff,         ah[mt][0], ah[mt][1], ah[mt][2], ah[mt][3]);
            ldsm4(aB + 16384 + aoff, al[mt][0], al[mt][1], al[mt][2], al[mt][3]);
        }
#pragma unroll
        for (int obp = 0; obp < 2; obp++) {
            uint32_t boff = sw128((uint32_t)((ob * 32 + obp * 16 + b_row2) * 128 + kb * 32 + b_kx2));
            uint32_t bh0, bh1, bh2, bh3, bl0, bl1, bl2, bl3;
            ldsm4(bB + boff,        bh0, bh1, bh2, bh3);
            ldsm4(bB + 8192 + boff, bl0, bl1, bl2, bl3);
#pragma unroll
            for (int mt = 0; mt < 2; mt++) {
                mma16816(d[mt][obp * 2],     ah[mt][0], ah[mt][1], ah[mt][2], ah[mt][3], bh0, bh1);
                mma16816(d[mt][obp * 2],     ah[mt][0], ah[mt][1], ah[mt][2], ah[mt][3], bl0, bl1);
                mma16816(d[mt][obp * 2],     al[mt][0], al[mt][1], al[mt][2], al[mt][3], bh0, bh1);
                mma16816(d[mt][obp * 2 + 1], ah[mt][0], ah[mt][1], ah[mt][2], ah[mt][3], bh2, bh3);
                mma16816(d[mt][obp * 2 + 1], ah[mt][0], ah[mt][1], ah[mt][2], ah[mt][3], bl2, bl3);
                mma16816(d[mt][obp * 2 + 1], al[mt][0], al[mt][1], al[mt][2], al[mt][3], bh2, bh3);
            }
        }
    };

    // ---- prologue ----
    prefetchCI(0, 0); copyB(0, 0); cpcommit(); cpwait0();
    __syncthreads();
    {
        const int4*   sCI = (const int4*)(smem + D_CI(0));
        const float4* sCW = (const float4*)(smem + D_CI(0) + 2048);
        uint32_t dA = sb + D_A(0);
#pragma unroll 2
        for (int it = 0; it < 8; it++) {
            int i = (it << 8) + t;
            int px = i >> 4, cg = i & 15;
            int4 ci = sCI[px];
            float4 cw = sCW[px];
            float4 v0 = *((const float4*)(xb + ((size_t)ci.x << 6)) + cg);
            float4 v1 = *((const float4*)(xb + ((size_t)ci.y << 6)) + cg);
            float4 v2 = *((const float4*)(xb + ((size_t)ci.z << 6)) + cg);
            float4 v3 = *((const float4*)(xb + ((size_t)ci.w << 6)) + cg);
            float r0 = cw.x * v0.x + cw.y * v1.x + cw.z * v2.x + cw.w * v3.x;
            float r1 = cw.x * v0.y + cw.y * v1.y + cw.z * v2.y + cw.w * v3.y;
            float r2 = cw.x * v0.z + cw.y * v1.z + cw.z * v2.z + cw.w * v3.z;
            float r3 = cw.x * v0.w + cw.y * v1.w + cw.z * v2.w + cw.w * v3.w;
            uint32_t h01, l01, h23, l23;
            hilo_pack(r0, r1, h01, l01);
            hilo_pack(r2, r3, h23, l23);
            uint32_t swo = sw128((uint32_t)(px * 128 + cg * 8));
            sts64(dA + swo, h01, h23);
            sts64(dA + 16384 + swo, l01, l23);
        }
    }
    prefetchCI(1, 1); cpcommit(); cpwait0();
    __syncthreads();

    // ---- main loop ----
#pragma unroll 1
    for (int tap = 0; tap < 9; tap++) {
        int s = tap & 1;
        uint32_t aB = sb + D_A(s), bB = sb + D_B(s);
        if (tap < 8) {
            copyB(tap + 1, s ^ 1);
            if (tap + 2 <= 8) prefetchCI(tap + 2, s);
            cpcommit();
        }
        uint32_t dA = sb + D_A(s ^ 1);
        if (tap < 8) issue2(s ^ 1, 0);
        do_kb(0, aB, bB);
        if (tap < 8) { flush2(dA); issue2(s ^ 1, 2); }
        do_kb(1, aB, bB);
        if (tap < 8) { flush2(dA); issue2(s ^ 1, 4); }
        do_kb(2, aB, bB);
        if (tap < 8) { flush2(dA); issue2(s ^ 1, 6); }
        do_kb(3, aB, bB);
        if (tap < 8) flush2(dA);
        cpwait0();
        __syncthreads();
    }

    // ---- epilogue: D frags -> out (NCHW) ----
    size_t bo = (size_t)b << 20;
#pragma unroll
    for (int mt = 0; mt < 2; mt++) {
        int r0 = hwbase + pxb * 32 + mt * 16 + (lane >> 2);
        int r1 = r0 + 8;
#pragma unroll
        for (int n8 = 0; n8 < 4; n8++) {
            int o0 = ob * 32 + n8 * 8 + (lane & 3) * 2;
            out[bo + (size_t)o0 * 16384 + r0]       = d[mt][n8][0];
            out[bo + (size_t)(o0 + 1) * 16384 + r0] = d[mt][n8][1];
            out[bo + (size_t)o0 * 16384 + r1]       = d[mt][n8][2];
            out[bo + (size_t)(o0 + 1) * 16384 + r1] = d[mt][n8][3];
        }
    }
}

// ---------------- launch ----------------
extern "C" void kernel_launch(void* const* d_in, const int* in_sizes, int n_in,
                              void* d_out, int out_size) {
    (void)in_sizes; (void)n_in; (void)out_size;
    const float* x      = (const float*)d_in[0];
    const float* w_conv = (const float*)d_in[1];
    const float* w_off  = (const float*)d_in[2];
    const float* w_msk  = (const float*)d_in[3];
    float* out = (float*)d_out;

    cudaFuncSetAttribute(k_conv,   cudaFuncAttributeMaxDynamicSharedMemorySize, CONV_SMEM);
    cudaFuncSetAttribute(k_deform, cudaFuncAttributeMaxDynamicSharedMemorySize, DEF_SMEM);

    k_prep<<<4312, 256>>>(x, w_conv, w_off, w_msk);
    k_conv<<<1024, 256, CONV_SMEM>>>();
    k_deform<<<1024, 256, DEF_SMEM>>>(out);
}

// round 14
// speedup vs baseline: 1.7890x; 1.0078x over previous
#include <cuda_runtime.h>
#include <cuda_bf16.h>
#include <cstdint>

#define HWsz 16384
#define NPIX (8 * HWsz)   // 131072 pixels

// -------- scratch --------
__device__ float            g_xt[(size_t)NPIX * 64];    // NHWC x (f32, for deform bilinear blend)
__device__ __nv_bfloat16    g_xh[(size_t)NPIX * 64];    // NHWC x bf16 hi
__device__ __nv_bfloat16    g_xl[(size_t)NPIX * 64];    // NHWC x bf16 lo
__device__ __align__(16) uint32_t g_wqs[9 * 4096];      // deform W: per tap 16KB (hi 8KB + lo 8KB), 64x64 bf16 SW128
__device__ __align__(16) uint32_t g_wom[9 * 2048];      // conv W: per tap 8KB (hi 4KB + lo 4KB), 32x64 bf16 SW128
__device__ int4   g_ci2[(size_t)9 * NPIX];              // corner indices, [tap][pixel]
__device__ float4 g_cw2[(size_t)9 * NPIX];              // corner weights, [tap][pixel]

// -------- helpers --------
__device__ __forceinline__ uint32_t smem_u32(const void* p) {
    return (uint32_t)__cvta_generic_to_shared(p);
}
__device__ __forceinline__ void sts64(uint32_t addr, uint32_t a, uint32_t b) {
    asm volatile("st.shared.v2.b32 [%0], {%1, %2};" :: "r"(addr), "r"(a), "r"(b) : "memory");
}
__device__ __forceinline__ uint32_t bf16x2_of(float hi, float lo) {
    uint32_t r; asm("cvt.rn.bf16x2.f32 %0, %1, %2;" : "=r"(r) : "f"(hi), "f"(lo)); return r;
}
__device__ __forceinline__ uint32_t sw128(uint32_t off) { return off ^ ((off >> 3) & 0x70); }

__device__ __forceinline__ void ldsm4(uint32_t addr, uint32_t& r0, uint32_t& r1, uint32_t& r2, uint32_t& r3) {
    asm volatile("ldmatrix.sync.aligned.m8n8.x4.shared.b16 {%0,%1,%2,%3}, [%4];"
                 : "=r"(r0), "=r"(r1), "=r"(r2), "=r"(r3) : "r"(addr));
}
__device__ __forceinline__ void mma16816(float* d, uint32_t a0, uint32_t a1, uint32_t a2, uint32_t a3,
                                         uint32_t b0, uint32_t b1) {
    asm volatile("mma.sync.aligned.m16n8k16.row.col.f32.bf16.bf16.f32 "
                 "{%0,%1,%2,%3}, {%4,%5,%6,%7}, {%8,%9}, {%0,%1,%2,%3};"
                 : "+f"(d[0]), "+f"(d[1]), "+f"(d[2]), "+f"(d[3])
                 : "r"(a0), "r"(a1), "r"(a2), "r"(a3), "r"(b0), "r"(b1));
}
__device__ __forceinline__ void hilo_pack(float r0, float r1, uint32_t& h, uint32_t& l) {
    h = bf16x2_of(r1, r0);
    float hi0 = __uint_as_float(h << 16);
    float hi1 = __uint_as_float(h & 0xFFFF0000u);
    l = bf16x2_of(r1 - hi1, r0 - hi0);
}
__device__ __forceinline__ void cpasync16(uint32_t dst, const void* src, int srcsize) {
    asm volatile("cp.async.ca.shared.global [%0], [%1], 16, %2;"
                 :: "r"(dst), "l"(src), "r"(srcsize) : "memory");
}
__device__ __forceinline__ void cpcommit() { asm volatile("cp.async.commit_group;" ::: "memory"); }
__device__ __forceinline__ void cpwait0()  { asm volatile("cp.async.wait_group 0;" ::: "memory"); }

// ---------------- kernel 1: fused prep (transpose + both weight packs) ----------------
__global__ void __launch_bounds__(256) k_prep(const float* __restrict__ x,
                                              const float* __restrict__ w_conv,
                                              const float* __restrict__ w_off,
                                              const float* __restrict__ w_msk) {
    __shared__ float sh[64][33];
    int blk = blockIdx.x;
    int tid = threadIdx.x;
    if (blk < 4096) {
        int b   = blk >> 9;
        int hw0 = (blk & 511) << 5;
#pragma unroll
        for (int i = 0; i < 8; i++) {
            int e = tid + i * 256;
            int c = e >> 5, wp = e & 31;
            sh[c][wp] = x[((size_t)(b * 64 + c) << 14) + hw0 + wp];
        }
        __syncthreads();
#pragma unroll
        for (int i = 0; i < 8; i++) {
            int e = tid + i * 256;
            int wp = e >> 6, c = e & 63;
            float v = sh[c][wp];
            size_t idx = (((size_t)b << 14) + hw0 + wp) * 64 + c;
            g_xt[idx] = v;
            __nv_bfloat16 hb = __float2bfloat16(v);
            g_xh[idx] = hb;
            g_xl[idx] = __float2bfloat16(v - __bfloat162float(hb));
        }
    } else if (blk < 4096 + 144) {
        int t = (blk - 4096) * 256 + tid;   // < 36864
        int tap = t >> 12;
        int r   = t & 4095;
        int o = r >> 6, c = r & 63;
        float w = w_conv[o * 576 + c * 9 + tap];
        __nv_bfloat16 hb = __float2bfloat16(w);
        __nv_bfloat16 lb = __float2bfloat16(w - __bfloat162float(hb));
        uint32_t swo = sw128(o * 128 + c * 2);
        char* base = (char*)g_wqs + tap * 16384;
        *(__nv_bfloat16*)(base + swo)        = hb;
        *(__nv_bfloat16*)(base + 8192 + swo) = lb;
    } else {
        int t = (blk - 4240) * 256 + tid;   // < 18432
        int tap = t >> 11;
        int r   = t & 2047;
        int o = r >> 6, c = r & 63;
        float w = 0.f;
        if (o < 18)      w = w_off[o * 576 + c * 9 + tap];
        else if (o < 27) w = w_msk[(o - 18) * 576 + c * 9 + tap];
        __nv_bfloat16 hb = __float2bfloat16(w);
        __nv_bfloat16 lb = __float2bfloat16(w - __bfloat162float(hb));
        uint32_t swo = sw128(o * 128 + c * 2);
        char* base = (char*)g_wom + tap * 8192;
        *(__nv_bfloat16*)(base + swo)        = hb;
        *(__nv_bfloat16*)(base + 4096 + swo) = lb;
    }
}

// ---------------- kernel 2: offset+mask conv via MMA, row-grouped A staging ----------------
#define CR(s)  ((s) * 34816)
#define CBB(s) (69632 + (s) * 8192)
#define CONV_SMEM 86016
__global__ void __launch_bounds__(256) k_conv() {
    extern __shared__ __align__(1024) char smem[];
    uint32_t sb = smem_u32(smem);

    int t = threadIdx.x, warp = t >> 5, lane = t & 31;
    int h = blockIdx.x & 127;
    int b = blockIdx.x >> 7;
    const __nv_bfloat16* xh = g_xh + ((size_t)b << 20);
    const __nv_bfloat16* xl = g_xl + ((size_t)b << 20);

    float d[4][4];
#pragma unroll
    for (int nb = 0; nb < 4; nb++)
#pragma unroll
        for (int i = 0; i < 4; i++) d[nb][i] = 0.f;

    int a_row = warp * 16 + (lane & 7) + ((lane >> 3) & 1) * 8;
    int a_kx  = ((lane >> 4) & 1) * 16;
    int b_row2 = ((lane >> 4) & 1) * 8 + (lane & 7);
    int b_kx2  = ((lane >> 3) & 1) * 16;

    auto copyRow = [&](int dy, int s) {
        int hh = h - 1 + dy;
        bool okh = (unsigned)hh < 128u;
        const __nv_bfloat16* rh = xh + ((size_t)(hh & 127) << 13);
        const __nv_bfloat16* rl = xl + ((size_t)(hh & 127) << 13);
        uint32_t dR = sb + CR(s);
        for (int i = t; i < 2080; i += 256) {
            int part = (i >= 1040) ? 1 : 0;
            int r = i - part * 1040;
            int slot = r >> 3, u = r & 7;
            int gx = slot - 1;
            bool ok = okh && ((unsigned)gx < 128u);
            const __nv_bfloat16* src = (part ? rl : rh) + ((gx & 127) << 6) + u * 8;
            uint32_t dst = dR + part * 17408 + sw128((uint32_t)(slot * 128 + u * 16));
            cpasync16(dst, src, ok ? 16 : 0);
        }
    };
    auto copyB = [&](int tap, int s) {
        const char* src = (const char*)g_wom + tap * 8192;
        uint32_t dB = sb + CBB(s);
#pragma unroll
        for (int i = 0; i < 2; i++) {
            int u = i * 256 + t;
            cpasync16(dB + u * 16, src + u * 16, 16);
        }
    };

    copyRow(0, 0); copyB(0, 0); cpcommit(); cpwait0();
    __syncthreads();

#pragma unroll 1
    for (int tap = 0; tap < 9; tap++) {
        int dy = tap / 3, sx = tap - dy * 3;
        int sB = tap & 1;
        if (tap < 8) copyB(tap + 1, sB ^ 1);
        if (tap == 0) copyRow(1, 1);
        if (tap == 3) copyRow(2, 0);
        if (tap < 8) cpcommit();

        uint32_t hiB = sb + CR(dy & 1), loB = hiB + 17408, bB = sb + CBB(sB);
#pragma unroll
        for (int kb = 0; kb < 4; kb++) {
            uint32_t aoff = sw128((uint32_t)((a_row + sx) * 128 + kb * 32 + a_kx));
            uint32_t ah0, ah1, ah2, ah3, al0, al1, al2, al3;
            ldsm4(hiB + aoff, ah0, ah1, ah2, ah3);
            ldsm4(loB + aoff, al0, al1, al2, al3);
#pragma unroll
            for (int nbp = 0; nbp < 2; nbp++) {
                uint32_t boff = sw128((uint32_t)((nbp * 16 + b_row2) * 128 + kb * 32 + b_kx2));
                uint32_t bh0, bh1, bh2, bh3, bl0, bl1, bl2, bl3;
                ldsm4(bB + boff, bh0, bh1, bh2, bh3);
                ldsm4(bB + 4096 + boff, bl0, bl1, bl2, bl3);
                mma16816(d[nbp * 2],     ah0, ah1, ah2, ah3, bh0, bh1);
                mma16816(d[nbp * 2],     ah0, ah1, ah2, ah3, bl0, bl1);
                mma16816(d[nbp * 2],     al0, al1, al2, al3, bh0, bh1);
                mma16816(d[nbp * 2 + 1], ah0, ah1, ah2, ah3, bh2, bh3);
                mma16816(d[nbp * 2 + 1], ah0, ah1, ah2, ah3, bl2, bl3);
                mma16816(d[nbp * 2 + 1], al0, al1, al2, al3, bh2, bh3);
            }
        }
        cpwait0();
        __syncthreads();
    }

    // transpose D through smem: sD[px][33]
    float* sD = (float*)smem;
    {
        int r0 = warp * 16 + (lane >> 2);
        int r1 = r0 + 8;
#pragma unroll
        for (int nb = 0; nb < 4; nb++) {
            int o0 = nb * 8 + (lane & 3) * 2;
            sD[r0 * 33 + o0]     = d[nb][0];
            sD[r0 * 33 + o0 + 1] = d[nb][1];
            sD[r1 * 33 + o0]     = d[nb][2];
            sD[r1 * 33 + o0 + 1] = d[nb][3];
        }
    }
    __syncthreads();

    // corner emit: all 256 threads; t<128 -> taps 0..4, t>=128 -> taps 5..8 of pixel t&127
    {
        int w = t & 127;
        int k0 = (t < 128) ? 0 : 5;
        int k1 = (t < 128) ? 5 : 9;
        const float* rr = sD + w * 33;
        int p = b * 16384 + h * 128 + w;
        for (int k = k0; k < k1; k++) {
            float oy = rr[2 * k], ox = rr[2 * k + 1];
            float m  = 1.f / (1.f + __expf(-rr[18 + k]));
            float py = (float)(h + k / 3 - 1) + oy;
            float px = (float)(w + k % 3 - 1) + ox;
            float y0f = floorf(py), x0f = floorf(px);
            float wy1 = py - y0f, wy0 = 1.f - wy1;
            float wx1 = px - x0f, wx0 = 1.f - wx1;
            int y0 = (int)y0f, x0i = (int)x0f;
            int y1 = y0 + 1, x1i = x0i + 1;
            bool vy0 = (unsigned)y0  < 128u, vy1 = (unsigned)y1  < 128u;
            bool vx0 = (unsigned)x0i < 128u, vx1 = (unsigned)x1i < 128u;
            int cy0 = min(max(y0, 0), 127), cy1 = min(max(y1, 0), 127);
            int cx0 = min(max(x0i, 0), 127), cx1 = min(max(x1i, 0), 127);
            int4 ci; float4 cw;
            ci.x = cy0 * 128 + cx0; cw.x = (vy0 && vx0) ? m * wy0 * wx0 : 0.f;
            ci.y = cy0 * 128 + cx1; cw.y = (vy0 && vx1) ? m * wy0 * wx1 : 0.f;
            ci.z = cy1 * 128 + cx0; cw.z = (vy1 && vx0) ? m * wy1 * wx0 : 0.f;
            ci.w = cy1 * 128 + cx1; cw.w = (vy1 && vx1) ? m * wy1 * wx1 : 0.f;
            g_ci2[(size_t)k * NPIX + p] = ci;
            g_cw2[(size_t)k * NPIX + p] = cw;
        }
    }
}

// ---------------- kernel 3: deform gather + mma, 32px x 32o warp tiles ----------------
#define D_A(s)  ((s) * 32768)
#define D_B(s)  (65536 + (s) * 16384)
#define D_CI(s) (98304 + (s) * 4096)
#define DEF_SMEM 106496
#define SDP 132   // epilogue sD row stride (floats)
__global__ void __launch_bounds__(256, 2) k_deform(float* __restrict__ out) {
    extern __shared__ __align__(1024) char smem[];
    uint32_t sb = smem_u32(smem);

    int t = threadIdx.x, warp = t >> 5, lane = t & 31;
    int P0 = blockIdx.x << 7;
    int b = P0 >> 14, hwbase = P0 & 16383;
    const float* xb = g_xt + ((size_t)b << 20);

    int pxb = warp & 3, ob = warp >> 2;
    int a_row0 = pxb * 32 + (lane & 7) + ((lane >> 3) & 1) * 8;
    int a_kx   = ((lane >> 4) & 1) * 16;
    int b_row2 = ((lane >> 4) & 1) * 8 + (lane & 7);
    int b_kx2  = ((lane >> 3) & 1) * 16;

    float d[2][4][4];
#pragma unroll
    for (int mt = 0; mt < 2; mt++)
#pragma unroll
        for (int nb = 0; nb < 4; nb++)
#pragma unroll
            for (int i = 0; i < 4; i++) d[mt][nb][i] = 0.f;

    auto prefetchCI = [&](int tap, int s) {
        uint32_t dst = sb + D_CI(s);
        if (t < 128) cpasync16(dst + t * 16, g_ci2 + (size_t)tap * NPIX + P0 + t, 16);
        else         cpasync16(dst + 2048 + (t - 128) * 16, g_cw2 + (size_t)tap * NPIX + P0 + (t - 128), 16);
    };
    auto copyB = [&](int tap, int s) {
        const char* src = (const char*)g_wqs + tap * 16384;
        uint32_t dB = sb + D_B(s);
#pragma unroll
        for (int i = 0; i < 4; i++) {
            int u = i * 256 + t;
            cpasync16(dB + u * 16, src + u * 16, 16);
        }
    };

    float4 vv[2][4]; float4 cwq[2]; uint32_t swoq[2];
    auto issue2 = [&](int ciS, int it0) {
        const int4*   sCI = (const int4*)(smem + D_CI(ciS));
        const float4* sCW = (const float4*)(smem + D_CI(ciS) + 2048);
#pragma unroll
        for (int q = 0; q < 2; q++) {
            int i = ((it0 + q) << 8) + t;
            int px = i >> 4, cg = i & 15;
            int4 ci = sCI[px];
            cwq[q]  = sCW[px];
            vv[q][0] = *((const float4*)(xb + ((size_t)ci.x << 6)) + cg);
            vv[q][1] = *((const float4*)(xb + ((size_t)ci.y << 6)) + cg);
            vv[q][2] = *((const float4*)(xb + ((size_t)ci.z << 6)) + cg);
            vv[q][3] = *((const float4*)(xb + ((size_t)ci.w << 6)) + cg);
            swoq[q] = sw128((uint32_t)(px * 128 + cg * 8));
        }
    };
    auto flush2 = [&](uint32_t dA) {
#pragma unroll
        for (int q = 0; q < 2; q++) {
            float4 cw = cwq[q];
            float r0 = cw.x * vv[q][0].x + cw.y * vv[q][1].x + cw.z * vv[q][2].x + cw.w * vv[q][3].x;
            float r1 = cw.x * vv[q][0].y + cw.y * vv[q][1].y + cw.z * vv[q][2].y + cw.w * vv[q][3].y;
            float r2 = cw.x * vv[q][0].z + cw.y * vv[q][1].z + cw.z * vv[q][2].z + cw.w * vv[q][3].z;
            float r3 = cw.x * vv[q][0].w + cw.y * vv[q][1].w + cw.z * vv[q][2].w + cw.w * vv[q][3].w;
            uint32_t h01, l01, h23, l23;
            hilo_pack(r0, r1, h01, l01);
            hilo_pack(r2, r3, h23, l23);
            sts64(dA + swoq[q], h01, h23);
            sts64(dA + 16384 + swoq[q], l01, l23);
        }
    };
    auto do_kb = [&](int kb, uint32_t aB, uint32_t bB) {
        uint32_t ah[2][4], al[2][4];
#pragma unroll
        for (int mt = 0; mt < 2; mt++) {
            uint32_t aoff = sw128((uint32_t)((a_row0 + mt * 16) * 128 + kb * 32 + a_kx));
            ldsm4(aB + aoff,         ah[mt][0], ah[mt][1], ah[mt][2], ah[mt][3]);
            ldsm4(aB + 16384 + aoff, al[mt][0], al[mt][1], al[mt][2], al[mt][3]);
        }
#pragma unroll
        for (int obp = 0; obp < 2; obp++) {
            uint32_t boff = sw128((uint32_t)((ob * 32 + obp * 16 + b_row2) * 128 + kb * 32 + b_kx2));
            uint32_t bh0, bh1, bh2, bh3, bl0, bl1, bl2, bl3;
            ldsm4(bB + boff,        bh0, bh1, bh2, bh3);
            ldsm4(bB + 8192 + boff, bl0, bl1, bl2, bl3);
#pragma unroll
            for (int mt = 0; mt < 2; mt++) {
                mma16816(d[mt][obp * 2],     ah[mt][0], ah[mt][1], ah[mt][2], ah[mt][3], bh0, bh1);
                mma16816(d[mt][obp * 2],     ah[mt][0], ah[mt][1], ah[mt][2], ah[mt][3], bl0, bl1);
                mma16816(d[mt][obp * 2],     al[mt][0], al[mt][1], al[mt][2], al[mt][3], bh0, bh1);
                mma16816(d[mt][obp * 2 + 1], ah[mt][0], ah[mt][1], ah[mt][2], ah[mt][3], bh2, bh3);
                mma16816(d[mt][obp * 2 + 1], ah[mt][0], ah[mt][1], ah[mt][2], ah[mt][3], bl2, bl3);
                mma16816(d[mt][obp * 2 + 1], al[mt][0], al[mt][1], al[mt][2], al[mt][3], bh2, bh3);
            }
        }
    };

    // ---- prologue ----
    prefetchCI(0, 0); copyB(0, 0); cpcommit(); cpwait0();
    __syncthreads();
    {
        const int4*   sCI = (const int4*)(smem + D_CI(0));
        const float4* sCW = (const float4*)(smem + D_CI(0) + 2048);
        uint32_t dA = sb + D_A(0);
#pragma unroll 2
        for (int it = 0; it < 8; it++) {
            int i = (it << 8) + t;
            int px = i >> 4, cg = i & 15;
            int4 ci = sCI[px];
            float4 cw = sCW[px];
            float4 v0 = *((const float4*)(xb + ((size_t)ci.x << 6)) + cg);
            float4 v1 = *((const float4*)(xb + ((size_t)ci.y << 6)) + cg);
            float4 v2 = *((const float4*)(xb + ((size_t)ci.z << 6)) + cg);
            float4 v3 = *((const float4*)(xb + ((size_t)ci.w << 6)) + cg);
            float r0 = cw.x * v0.x + cw.y * v1.x + cw.z * v2.x + cw.w * v3.x;
            float r1 = cw.x * v0.y + cw.y * v1.y + cw.z * v2.y + cw.w * v3.y;
            float r2 = cw.x * v0.z + cw.y * v1.z + cw.z * v2.z + cw.w * v3.z;
            float r3 = cw.x * v0.w + cw.y * v1.w + cw.z * v2.w + cw.w * v3.w;
            uint32_t h01, l01, h23, l23;
            hilo_pack(r0, r1, h01, l01);
            hilo_pack(r2, r3, h23, l23);
            uint32_t swo = sw128((uint32_t)(px * 128 + cg * 8));
            sts64(dA + swo, h01, h23);
            sts64(dA + 16384 + swo, l01, l23);
        }
    }
    prefetchCI(1, 1); cpcommit(); cpwait0();
    __syncthreads();

    // ---- main loop ----
#pragma unroll 1
    for (int tap = 0; tap < 9; tap++) {
        int s = tap & 1;
        uint32_t aB = sb + D_A(s), bB = sb + D_B(s);
        if (tap < 8) {
            copyB(tap + 1, s ^ 1);
            if (tap + 2 <= 8) prefetchCI(tap + 2, s);
            cpcommit();
        }
        uint32_t dA = sb + D_A(s ^ 1);
        if (tap < 8) issue2(s ^ 1, 0);
        do_kb(0, aB, bB);
        if (tap < 8) { flush2(dA); issue2(s ^ 1, 2); }
        do_kb(1, aB, bB);
        if (tap < 8) { flush2(dA); issue2(s ^ 1, 4); }
        do_kb(2, aB, bB);
        if (tap < 8) { flush2(dA); issue2(s ^ 1, 6); }
        do_kb(3, aB, bB);
        if (tap < 8) flush2(dA);
        cpwait0();
        __syncthreads();
    }

    // ---- epilogue: transpose through smem -> coalesced float4 STG ----
    // phase 1: STS d frags into sD[o][SDP] (conflict-free: bank = 8*(lane&3)+(lane>>2))
    float* sD = (float*)smem;
#pragma unroll
    for (int mt = 0; mt < 2; mt++) {
        int r0 = pxb * 32 + mt * 16 + (lane >> 2);
        int r1 = r0 + 8;
#pragma unroll
        for (int n8 = 0; n8 < 4; n8++) {
            int o0 = ob * 32 + n8 * 8 + (lane & 3) * 2;
            sD[o0 * SDP + r0]       = d[mt][n8][0];
            sD[(o0 + 1) * SDP + r0] = d[mt][n8][1];
            sD[o0 * SDP + r1]       = d[mt][n8][2];
            sD[(o0 + 1) * SDP + r1] = d[mt][n8][3];
        }
    }
    __syncthreads();
    // phase 2: dense float4 stores, 8 o-rows per iteration (lanes span px)
    {
        size_t bo = (size_t)b << 20;
        int og = t >> 5;            // 0..7
        int pxq = (t & 31) * 4;     // 0,4,...,124
#pragma unroll
        for (int it = 0; it < 8; it++) {
            int o = it * 8 + og;
            float4 v = *(const float4*)(sD + o * SDP + pxq);
            *(float4*)(out + bo + (size_t)o * 16384 + hwbase + pxq) = v;
        }
    }
}

// ---------------- launch ----------------
extern "C" void kernel_launch(void* const* d_in, const int* in_sizes, int n_in,
                              void* d_out, int out_size) {
    (void)in_sizes; (void)n_in; (void)out_size;
    const float* x      = (const float*)d_in[0];
    const float* w_conv = (const float*)d_in[1];
    const float* w_off  = (const float*)d_in[2];
    const float* w_msk  = (const float*)d_in[3];
    float* out = (float*)d_out;

    cudaFuncSetAttribute(k_conv,   cudaFuncAttributeMaxDynamicSharedMemorySize, CONV_SMEM);
    cudaFuncSetAttribute(k_deform, cudaFuncAttributeMaxDynamicSharedMemorySize, DEF_SMEM);

    k_prep<<<4312, 256>>>(x, w_conv, w_off, w_msk);
    k_conv<<<1024, 256, CONV_SMEM>>>();
    k_deform<<<1024, 256, DEF_SMEM>>>(out);
}